// round 4
// baseline (speedup 1.0000x reference)
#include <cuda_runtime.h>
#include <cstdint>

// Problem constants
#define BB   128   // batch
#define INW  256   // input width
#define HH   1024  // hidden
#define NP   512   // pairs per A layer
#define LP   128   // number of (A,B) layer pairs (L=256 layers total)
#define FULLMASK 0xffffffffu

// Static device scratch (padded +2 layers so depth-2 prefetch never faults)
__device__ float4 g_trigA[LP + 2][NP];      // {cos t0, sin t0, cos t1, sin t1}
__device__ float4 g_trigB[LP + 2][NP];      // idx 511 = identity MZI
__device__ float  g_pR[4][BB * HH];         // GEMM partials per K-chunk
__device__ float  g_pI[4][BB * HH];

// ---------------------------------------------------------------------------
// Kernel 1: blocks [0,128) = complex GEMM (K-split x4, N-tiles of 32)
//           blocks [128,256) = trig table build (one block per layer pair)
// ---------------------------------------------------------------------------
__global__ __launch_bounds__(256) void k1(
    const float* __restrict__ inR, const float* __restrict__ inI,
    const float* __restrict__ wR,  const float* __restrict__ wI,
    const float* __restrict__ A0,  const float* __restrict__ A1,
    const float* __restrict__ B0,  const float* __restrict__ B1)
{
    const int bid = blockIdx.x, tid = threadIdx.x;

    if (bid >= 128) {
        const int k = bid - 128;
        for (int idx = tid; idx < NP; idx += 256) {
            float c0, s0, c1, s1;
            sincosf(A0[k * NP + idx], &s0, &c0);
            sincosf(A1[k * NP + idx], &s1, &c1);
            g_trigA[k][idx] = make_float4(c0, s0, c1, s1);
        }
        for (int idx = tid; idx < NP; idx += 256) {
            float ang0 = (idx < NP - 1) ? B0[k * (NP - 1) + idx] : 0.f;
            float ang1 = (idx < NP - 1) ? B1[k * (NP - 1) + idx] : 0.f;
            float c0, s0, c1, s1;
            sincosf(ang0, &s0, &c0);
            sincosf(ang1, &s1, &c1);
            g_trigB[k][idx] = make_float4(c0, s0, c1, s1);
        }
        return;
    }

    // ---- complex GEMM: tile M=128, N=32, K-chunk=64 ----
    const int kc = bid >> 5, nt = bid & 31;
    const int k0 = kc * 64, n0 = nt * 32;

    __shared__ float sXR[32][132], sXI[32][132];
    __shared__ float sWR[32][33],  sWI[32][33];

    float accR[8][2], accI[8][2];
    #pragma unroll
    for (int r = 0; r < 8; r++)
        #pragma unroll
        for (int c = 0; c < 2; c++) { accR[r][c] = 0.f; accI[r][c] = 0.f; }

    const int mi = tid >> 4, ni = tid & 15;
    const int lm = tid & 127, kh = (tid >> 7) * 16;
    const int wn = tid >> 3,  wk = (tid & 7) * 4;

    for (int ks = 0; ks < 64; ks += 32) {
        __syncthreads();
        #pragma unroll
        for (int j = 0; j < 4; j++) {
            const int kk = kh + j * 4;
            float4 vR = *(const float4*)(inR + lm * INW + k0 + ks + kk);
            float4 vI = *(const float4*)(inI + lm * INW + k0 + ks + kk);
            sXR[kk+0][lm] = vR.x; sXR[kk+1][lm] = vR.y;
            sXR[kk+2][lm] = vR.z; sXR[kk+3][lm] = vR.w;
            sXI[kk+0][lm] = vI.x; sXI[kk+1][lm] = vI.y;
            sXI[kk+2][lm] = vI.z; sXI[kk+3][lm] = vI.w;
        }
        {
            float4 vR = *(const float4*)(wR + (n0 + wn) * INW + k0 + ks + wk);
            float4 vI = *(const float4*)(wI + (n0 + wn) * INW + k0 + ks + wk);
            sWR[wk+0][wn] = vR.x; sWR[wk+1][wn] = vR.y;
            sWR[wk+2][wn] = vR.z; sWR[wk+3][wn] = vR.w;
            sWI[wk+0][wn] = vI.x; sWI[wk+1][wn] = vI.y;
            sWI[wk+2][wn] = vI.z; sWI[wk+3][wn] = vI.w;
        }
        __syncthreads();

        #pragma unroll 8
        for (int kk = 0; kk < 32; kk++) {
            float aRv[8], aIv[8], bRv[2], bIv[2];
            *(float4*)&aRv[0] = *(const float4*)&sXR[kk][mi * 8];
            *(float4*)&aRv[4] = *(const float4*)&sXR[kk][mi * 8 + 4];
            *(float4*)&aIv[0] = *(const float4*)&sXI[kk][mi * 8];
            *(float4*)&aIv[4] = *(const float4*)&sXI[kk][mi * 8 + 4];
            bRv[0] = sWR[kk][ni*2]; bRv[1] = sWR[kk][ni*2+1];
            bIv[0] = sWI[kk][ni*2]; bIv[1] = sWI[kk][ni*2+1];
            #pragma unroll
            for (int r = 0; r < 8; r++)
                #pragma unroll
                for (int c = 0; c < 2; c++) {
                    accR[r][c] += aRv[r]*bRv[c] - aIv[r]*bIv[c];
                    accI[r][c] += aRv[r]*bIv[c] + aIv[r]*bRv[c];
                }
        }
    }

    #pragma unroll
    for (int r = 0; r < 8; r++) {
        const int m = mi * 8 + r;
        #pragma unroll
        for (int c = 0; c < 2; c++) {
            g_pR[kc][m * HH + n0 + ni*2 + c] = accR[r][c];
            g_pI[kc][m * HH + n0 + ni*2 + c] = accI[r][c];
        }
    }
}

// ---------------------------------------------------------------------------
// helpers
// ---------------------------------------------------------------------------
__device__ __forceinline__ float4 ldg_v4_pinned(const float4* p) {
    float4 v;
    asm volatile("ld.global.nc.v4.f32 {%0,%1,%2,%3}, [%4];"
                 : "=f"(v.x), "=f"(v.y), "=f"(v.z), "=f"(v.w) : "l"(p));
    return v;
}

// predicated publish: single volatile STS.128 with tag in .w, no branch
__device__ __forceinline__ void pub_pred(uint32_t addr, int pred,
                                         float x, float y, float z, uint32_t tag) {
    asm volatile("{\n\t"
                 ".reg .pred p;\n\t"
                 "setp.ne.s32 p, %0, 0;\n\t"
                 "@p st.volatile.shared.v4.f32 [%1], {%2,%3,%4,%5};\n\t"
                 "}"
                 :: "r"(pred), "r"(addr), "f"(x), "f"(y), "f"(z),
                    "f"(__uint_as_float(tag))
                 : "memory");
}

// convergent whole-warp broadcast spin until slot tag matches
__device__ __forceinline__ float4 spin4(uint32_t addr, uint32_t tag) {
    float4 v;
    do {
        asm volatile("ld.volatile.shared.v4.f32 {%0,%1,%2,%3}, [%4];"
                     : "=f"(v.x), "=f"(v.y), "=f"(v.z), "=f"(v.w) : "r"(addr));
    } while (__float_as_uint(v.w) != tag);
    return v;
}

// ---------------------------------------------------------------------------
// Kernel 2: Clements mesh — NO CTA barriers in the loop.
// Intra-warp exchange via shfl; 16 warp boundaries via tagged smem slots.
// ---------------------------------------------------------------------------
__global__ __launch_bounds__(512, 1) void k2(
    const float* __restrict__ stR, const float* __restrict__ stI,
    const float* __restrict__ bR,  const float* __restrict__ bI,
    const float* __restrict__ om,  const float* __restrict__ mb,
    float* __restrict__ out)
{
    const int b = blockIdx.x, t = threadIdx.x;
    const int w = t >> 5, l = t & 31;

    __shared__ float4 bndA[2][16];   // post-A (ar,ai) of lane0 of warp w+1
    __shared__ float4 bndU[2][16];   // u = {s1*bpr, s1*bpi, c1} of lane31 of warp w

    if (t < 32)       ((float4*)bndA)[t]      = make_float4(0.f, 0.f, 0.f, 0.f);
    else if (t < 64)  ((float4*)bndU)[t - 32] = make_float4(0.f, 0.f, 0.f, 0.f);
    __syncthreads();   // only barrier in the kernel

    // thread t owns channels (2t, 2t+1)
    float2 vr = ((const float2*)(stR + b * HH))[t];
    float2 vi = ((const float2*)(stI + b * HH))[t];
    float ar = vr.x, br = vr.y, ai = vi.x, bi = vi.y;

    const uint32_t baseA = (uint32_t)__cvta_generic_to_shared(bndA);
    const uint32_t baseU = (uint32_t)__cvta_generic_to_shared(bndU);
    const uint32_t slotPubA  = (uint32_t)(((w + 15) & 15) * 16); // warp w lane0 -> consumed by warp w-1 (ring)
    const uint32_t slotRdA   = (uint32_t)(w * 16);
    const uint32_t slotPubU  = (uint32_t)(w * 16);
    const uint32_t slotRdU   = (uint32_t)(((w + 15) & 15) * 16);
    const int isL0 = (l == 0), isL31 = (l == 31), isT0 = (t == 0);

    // depth-2 trig prefetch
    const float4* pA = &g_trigA[0][t];
    const float4* pB = &g_trigB[0][t];
    float4 tA0 = ldg_v4_pinned(pA);
    float4 tB0 = ldg_v4_pinned(pB);
    float4 tA1 = ldg_v4_pinned(pA + NP);
    float4 tB1 = ldg_v4_pinned(pB + NP);

    #pragma unroll 2
    for (int k = 0; k < LP; k++) {
        const uint32_t tag = (uint32_t)(k + 1);
        const uint32_t boff = (uint32_t)((k & 1) << 8);   // parity * 16 slots * 16B

        float4 ta = tA0, tb = tB0;
        tA0 = tA1; tB0 = tB1;
        tA1 = ldg_v4_pinned(pA + (k + 2) * NP);
        tB1 = ldg_v4_pinned(pB + (k + 2) * NP);

        // ---- layer A: pair (2t, 2t+1), thread-local ----
        float pr  = ta.x*ar - ta.y*ai;
        float pii = ta.y*ar + ta.x*ai;
        float nar = ta.z*pr  - ta.w*bi;
        float nai = ta.z*pii + ta.w*br;
        float nbr = ta.z*br  - ta.w*pii;
        float nbi = ta.z*bi  + ta.w*pr;
        ar = nar; ai = nai; br = nbr; bi = nbi;

        // lane0 publishes its post-A (ar,ai) for the left neighbor warp
        pub_pred(baseA + boff + slotPubA, isL0, ar, ai, 0.f, tag);

        // ---- layer B: phase-shift own a-arm (channel 2t+1) ----
        float bpr = tb.x*br - tb.y*bi;
        float bpi = tb.y*br + tb.x*bi;
        float myux = tb.w*bpr, myuy = tb.w*bpi, myuz = tb.z;

        // lane31 publishes u for the right neighbor warp
        pub_pred(baseU + boff + slotPubU, isL31, myux, myuy, myuz, tag);

        // intra-warp exchange (all lanes converged)
        float shNaX = __shfl_down_sync(FULLMASK, ar, 1);
        float shNaY = __shfl_down_sync(FULLMASK, ai, 1);
        float shUx  = __shfl_up_sync(FULLMASK, myux, 1);
        float shUy  = __shfl_up_sync(FULLMASK, myuy, 1);
        float shUz  = __shfl_up_sync(FULLMASK, myuz, 1);

        // boundary values (convergent whole-warp broadcast spins)
        float4 sA = spin4(baseA + boff + slotRdA, tag);
        float4 sU = spin4(baseU + boff + slotRdU, tag);

        float naX = isL31 ? sA.x : shNaX;   // t=511: tb.w==0 so garbage is harmless
        float naY = isL31 ? sA.y : shNaY;
        float ux  = isL0 ? sU.x : shUx;
        float uy  = isL0 ? sU.y : shUy;
        float uz  = isL0 ? sU.z : shUz;
        ux = isT0 ? 0.f : ux;               // t=0: identity (channel 0 passes)
        uy = isT0 ? 0.f : uy;
        uz = isT0 ? 1.f : uz;

        // a' of MZI(2t+1, 2t+2): new channel 2t+1 (mine)
        float obr = tb.z*bpr - tb.w*naY;
        float obi = tb.z*bpi + tb.w*naX;
        // b' of MZI(2t-1, 2t): new channel 2t (mine), via left neighbor's u
        float oar = uz*ar - uy;
        float oai = uz*ai + ux;

        br = obr; bi = obi; ar = oar; ai = oai;
    }

    // ---- epilogue ----
    const int ch = 2 * t;
    float ihR0 = bR[ch],     ihI0 = bI[ch];
    float ihR1 = bR[ch + 1], ihI1 = bI[ch + 1];
    #pragma unroll
    for (int c = 0; c < 4; c++) {
        float2 pr2 = ((const float2*)&g_pR[c][b * HH])[t];
        float2 pi2 = ((const float2*)&g_pI[c][b * HH])[t];
        ihR0 += pr2.x; ihR1 += pr2.y;
        ihI0 += pi2.x; ihI1 += pi2.y;
    }

    float co0, so0, co1, so1;
    sincosf(om[ch],     &so0, &co0);
    sincosf(om[ch + 1], &so1, &co1);

    float zr0 = ihR0 + co0*ar - so0*ai;
    float zi0 = ihI0 + so0*ar + co0*ai;
    float zr1 = ihR1 + co1*br - so1*bi;
    float zi1 = ihI1 + so1*br + co1*bi;

    float mag0 = sqrtf(zr0*zr0 + zi0*zi0);
    float mag1 = sqrtf(zr1*zr1 + zi1*zi1);
    float sc0 = fmaxf(mag0 + mb[ch],     0.f) / fmaxf(mag0, 1e-8f);
    float sc1 = fmaxf(mag1 + mb[ch + 1], 0.f) / fmaxf(mag1, 1e-8f);

    ((float2*)(out + b * HH))[t]           = make_float2(sc0*zr0, sc1*zr1);
    ((float2*)(out + BB * HH + b * HH))[t] = make_float2(sc0*zi0, sc1*zi1);
}

// ---------------------------------------------------------------------------
extern "C" void kernel_launch(void* const* d_in, const int* in_sizes, int n_in,
                              void* d_out, int out_size)
{
    const float* inR = (const float*)d_in[0];
    const float* inI = (const float*)d_in[1];
    const float* stR = (const float*)d_in[2];
    const float* stI = (const float*)d_in[3];
    const float* wR  = (const float*)d_in[4];
    const float* wI  = (const float*)d_in[5];
    const float* bR  = (const float*)d_in[6];
    const float* bI  = (const float*)d_in[7];
    const float* A0  = (const float*)d_in[8];
    const float* A1  = (const float*)d_in[9];
    const float* B0  = (const float*)d_in[10];
    const float* B1  = (const float*)d_in[11];
    const float* om  = (const float*)d_in[12];
    const float* mb  = (const float*)d_in[13];
    float* out = (float*)d_out;

    k1<<<256, 256>>>(inR, inI, wR, wI, A0, A1, B0, B1);
    k2<<<128, 512>>>(stR, stI, bR, bI, om, mb, out);
}

// round 5
// speedup vs baseline: 1.0557x; 1.0557x over previous
#include <cuda_runtime.h>
#include <cstdint>

// Problem constants
#define BB   128   // batch
#define INW  256   // input width
#define HH   1024  // hidden
#define NP   512   // pairs per A layer
#define LP   128   // number of (A,B) layer pairs (L=256 layers total)
#define FULLMASK 0xffffffffu

// Static device scratch (padded +2 layers so depth-2 prefetch never faults)
__device__ float4 g_trigA[LP + 2][NP];      // {cos t0, sin t0, cos t1, sin t1}
__device__ float4 g_trigB[LP + 2][NP];      // idx 511 = identity MZI
__device__ float  g_pR[4][BB * HH];         // GEMM partials per K-chunk
__device__ float  g_pI[4][BB * HH];

// ---------------------------------------------------------------------------
// Kernel 1: blocks [0,128) = complex GEMM (K-split x4, N-tiles of 32)
//           blocks [128,256) = trig table build (one block per layer pair)
// ---------------------------------------------------------------------------
__global__ __launch_bounds__(256) void k1(
    const float* __restrict__ inR, const float* __restrict__ inI,
    const float* __restrict__ wR,  const float* __restrict__ wI,
    const float* __restrict__ A0,  const float* __restrict__ A1,
    const float* __restrict__ B0,  const float* __restrict__ B1)
{
    const int bid = blockIdx.x, tid = threadIdx.x;

    if (bid >= 128) {
        const int k = bid - 128;
        for (int idx = tid; idx < NP; idx += 256) {
            float c0, s0, c1, s1;
            sincosf(A0[k * NP + idx], &s0, &c0);
            sincosf(A1[k * NP + idx], &s1, &c1);
            g_trigA[k][idx] = make_float4(c0, s0, c1, s1);
        }
        for (int idx = tid; idx < NP; idx += 256) {
            float ang0 = (idx < NP - 1) ? B0[k * (NP - 1) + idx] : 0.f;
            float ang1 = (idx < NP - 1) ? B1[k * (NP - 1) + idx] : 0.f;
            float c0, s0, c1, s1;
            sincosf(ang0, &s0, &c0);
            sincosf(ang1, &s1, &c1);
            g_trigB[k][idx] = make_float4(c0, s0, c1, s1);
        }
        return;
    }

    // ---- complex GEMM: tile M=128, N=32, K-chunk=64 ----
    const int kc = bid >> 5, nt = bid & 31;
    const int k0 = kc * 64, n0 = nt * 32;

    __shared__ float sXR[32][132], sXI[32][132];
    __shared__ float sWR[32][33],  sWI[32][33];

    float accR[8][2], accI[8][2];
    #pragma unroll
    for (int r = 0; r < 8; r++)
        #pragma unroll
        for (int c = 0; c < 2; c++) { accR[r][c] = 0.f; accI[r][c] = 0.f; }

    const int mi = tid >> 4, ni = tid & 15;
    const int lm = tid & 127, kh = (tid >> 7) * 16;
    const int wn = tid >> 3,  wk = (tid & 7) * 4;

    for (int ks = 0; ks < 64; ks += 32) {
        __syncthreads();
        #pragma unroll
        for (int j = 0; j < 4; j++) {
            const int kk = kh + j * 4;
            float4 vR = *(const float4*)(inR + lm * INW + k0 + ks + kk);
            float4 vI = *(const float4*)(inI + lm * INW + k0 + ks + kk);
            sXR[kk+0][lm] = vR.x; sXR[kk+1][lm] = vR.y;
            sXR[kk+2][lm] = vR.z; sXR[kk+3][lm] = vR.w;
            sXI[kk+0][lm] = vI.x; sXI[kk+1][lm] = vI.y;
            sXI[kk+2][lm] = vI.z; sXI[kk+3][lm] = vI.w;
        }
        {
            float4 vR = *(const float4*)(wR + (n0 + wn) * INW + k0 + ks + wk);
            float4 vI = *(const float4*)(wI + (n0 + wn) * INW + k0 + ks + wk);
            sWR[wk+0][wn] = vR.x; sWR[wk+1][wn] = vR.y;
            sWR[wk+2][wn] = vR.z; sWR[wk+3][wn] = vR.w;
            sWI[wk+0][wn] = vI.x; sWI[wk+1][wn] = vI.y;
            sWI[wk+2][wn] = vI.z; sWI[wk+3][wn] = vI.w;
        }
        __syncthreads();

        #pragma unroll 8
        for (int kk = 0; kk < 32; kk++) {
            float aRv[8], aIv[8], bRv[2], bIv[2];
            *(float4*)&aRv[0] = *(const float4*)&sXR[kk][mi * 8];
            *(float4*)&aRv[4] = *(const float4*)&sXR[kk][mi * 8 + 4];
            *(float4*)&aIv[0] = *(const float4*)&sXI[kk][mi * 8];
            *(float4*)&aIv[4] = *(const float4*)&sXI[kk][mi * 8 + 4];
            bRv[0] = sWR[kk][ni*2]; bRv[1] = sWR[kk][ni*2+1];
            bIv[0] = sWI[kk][ni*2]; bIv[1] = sWI[kk][ni*2+1];
            #pragma unroll
            for (int r = 0; r < 8; r++)
                #pragma unroll
                for (int c = 0; c < 2; c++) {
                    accR[r][c] += aRv[r]*bRv[c] - aIv[r]*bIv[c];
                    accI[r][c] += aRv[r]*bIv[c] + aIv[r]*bRv[c];
                }
        }
    }

    #pragma unroll
    for (int r = 0; r < 8; r++) {
        const int m = mi * 8 + r;
        #pragma unroll
        for (int c = 0; c < 2; c++) {
            g_pR[kc][m * HH + n0 + ni*2 + c] = accR[r][c];
            g_pI[kc][m * HH + n0 + ni*2 + c] = accI[r][c];
        }
    }
}

// ---------------------------------------------------------------------------
// helpers
// ---------------------------------------------------------------------------
__device__ __forceinline__ float4 ldg_v4_pinned(const float4* p) {
    float4 v;
    asm volatile("ld.global.nc.v4.f32 {%0,%1,%2,%3}, [%4];"
                 : "=f"(v.x), "=f"(v.y), "=f"(v.z), "=f"(v.w) : "l"(p));
    return v;
}

__device__ __forceinline__ void pub_pred(uint32_t addr, int pred,
                                         float x, float y, float z, uint32_t tag) {
    asm volatile("{\n\t"
                 ".reg .pred p;\n\t"
                 "setp.ne.s32 p, %0, 0;\n\t"
                 "@p st.volatile.shared.v4.f32 [%1], {%2,%3,%4,%5};\n\t"
                 "}"
                 :: "r"(pred), "r"(addr), "f"(x), "f"(y), "f"(z),
                    "f"(__uint_as_float(tag))
                 : "memory");
}

__device__ __forceinline__ float4 ldvol4(uint32_t addr) {
    float4 v;
    asm volatile("ld.volatile.shared.v4.f32 {%0,%1,%2,%3}, [%4];"
                 : "=f"(v.x), "=f"(v.y), "=f"(v.z), "=f"(v.w) : "r"(addr));
    return v;
}

// ---------------------------------------------------------------------------
// Kernel 2: Clements mesh — 256 threads, 4 channels/thread.
// Layer A (2 MZIs) and middle B MZI fully thread-local; only 1 edge MZI
// crosses threads (shfl), 8 warp boundaries via tagged smem slots.
// ---------------------------------------------------------------------------
__global__ __launch_bounds__(256, 1) void k2(
    const float* __restrict__ stR, const float* __restrict__ stI,
    const float* __restrict__ bR,  const float* __restrict__ bI,
    const float* __restrict__ om,  const float* __restrict__ mb,
    float* __restrict__ out)
{
    const int b = blockIdx.x, t = threadIdx.x;
    const int w = t >> 5, l = t & 31;

    __shared__ float4 bndA[2][8];   // post-A c0 of lane0 of warp w+1 (ring)
    __shared__ float4 bndU[2][8];   // u of lane31 of warp w

    if (t < 16)       ((float4*)bndA)[t]      = make_float4(0.f, 0.f, 0.f, 0.f);
    else if (t < 32)  ((float4*)bndU)[t - 16] = make_float4(0.f, 0.f, 0.f, 0.f);
    __syncthreads();   // only CTA barrier

    // thread t owns channels 4t .. 4t+3
    float4 xr = ((const float4*)(stR + b * HH))[t];
    float4 xi = ((const float4*)(stI + b * HH))[t];
    float c0r = xr.x, c1r = xr.y, c2r = xr.z, c3r = xr.w;
    float c0i = xi.x, c1i = xi.y, c2i = xi.z, c3i = xi.w;

    const uint32_t baseA = (uint32_t)__cvta_generic_to_shared(bndA);
    const uint32_t baseU = (uint32_t)__cvta_generic_to_shared(bndU);
    const uint32_t sPubA = (uint32_t)(((w + 7) & 7) * 16);
    const uint32_t sRdA  = (uint32_t)(w * 16);
    const uint32_t sPubU = (uint32_t)(w * 16);
    const uint32_t sRdU  = (uint32_t)(((w + 7) & 7) * 16);
    const int isL0 = (l == 0), isL31 = (l == 31), isT0 = (t == 0);

    // depth-2 trig prefetch; thread t uses pair indices 2t, 2t+1 (contiguous)
    const float4* pA = &g_trigA[0][2 * t];
    const float4* pB = &g_trigB[0][2 * t];
    float4 a0A = ldg_v4_pinned(pA),       a1A = ldg_v4_pinned(pA + 1);
    float4 b0A = ldg_v4_pinned(pB),       b1A = ldg_v4_pinned(pB + 1);
    float4 a0B = ldg_v4_pinned(pA + NP),  a1B = ldg_v4_pinned(pA + NP + 1);
    float4 b0B = ldg_v4_pinned(pB + NP),  b1B = ldg_v4_pinned(pB + NP + 1);

    #pragma unroll 2
    for (int k = 0; k < LP; k++) {
        const uint32_t tag  = (uint32_t)(k + 1);
        const uint32_t boff = (uint32_t)((k & 1) << 7);   // parity * 8 slots * 16B

        float4 tA0 = a0A, tA1 = a1A, tB0 = b0A, tB1 = b1A;
        a0A = a0B; a1A = a1B; b0A = b0B; b1A = b1B;
        a0B = ldg_v4_pinned(pA + (k + 2) * NP);
        a1B = ldg_v4_pinned(pA + (k + 2) * NP + 1);
        b0B = ldg_v4_pinned(pB + (k + 2) * NP);
        b1B = ldg_v4_pinned(pB + (k + 2) * NP + 1);

        // ---- layer A, MZI (c0,c1) ----
        {
            float pr = tA0.x*c0r - tA0.y*c0i;
            float pi = tA0.y*c0r + tA0.x*c0i;
            float n0r = tA0.z*pr  - tA0.w*c1i;
            float n0i = tA0.z*pi  + tA0.w*c1r;
            float n1r = tA0.z*c1r - tA0.w*pi;
            float n1i = tA0.z*c1i + tA0.w*pr;
            c0r = n0r; c0i = n0i; c1r = n1r; c1i = n1i;
        }
        // early publish: lane0's post-A c0 for the left neighbor warp
        pub_pred(baseA + boff + sPubA, isL0, c0r, c0i, 0.f, tag);

        // ---- layer A, MZI (c2,c3) ----
        {
            float pr = tA1.x*c2r - tA1.y*c2i;
            float pi = tA1.y*c2r + tA1.x*c2i;
            float n2r = tA1.z*pr  - tA1.w*c3i;
            float n2i = tA1.z*pi  + tA1.w*c3r;
            float n3r = tA1.z*c3r - tA1.w*pi;
            float n3i = tA1.z*c3i + tA1.w*pr;
            c2r = n2r; c2i = n2i; c3r = n3r; c3i = n3i;
        }

        // ---- edge B MZI (c3, neighbor c0): phase + u, publish ----
        float p3r = tB1.x*c3r - tB1.y*c3i;
        float p3i = tB1.y*c3r + tB1.x*c3i;
        float u3x = tB1.w*p3r, u3y = tB1.w*p3i, u3z = tB1.z;
        pub_pred(baseU + boff + sPubU, isL31, u3x, u3y, u3z, tag);

        // intra-warp exchange
        float naXs = __shfl_down_sync(FULLMASK, c0r, 1);
        float naYs = __shfl_down_sync(FULLMASK, c0i, 1);
        float uxs  = __shfl_up_sync(FULLMASK, u3x, 1);
        float uys  = __shfl_up_sync(FULLMASK, u3y, 1);
        float uzs  = __shfl_up_sync(FULLMASK, u3z, 1);

        // ---- middle B MZI (c1,c2): thread-local, fills shfl latency ----
        {
            float pmr = tB0.x*c1r - tB0.y*c1i;
            float pmi = tB0.y*c1r + tB0.x*c1i;
            float n1r = tB0.z*pmr - tB0.w*c2i;
            float n1i = tB0.z*pmi + tB0.w*c2r;
            float n2r = tB0.z*c2r - tB0.w*pmi;
            float n2i = tB0.z*c2i + tB0.w*pmr;
            c1r = n1r; c1i = n1i; c2r = n2r; c2i = n2i;
        }

        // combined boundary spin (warp-uniform broadcast addresses)
        float4 sA, sU;
        do {
            sA = ldvol4(baseA + boff + sRdA);
            sU = ldvol4(baseU + boff + sRdU);
        } while (__float_as_uint(sA.w) != tag || __float_as_uint(sU.w) != tag);

        float naX = isL31 ? sA.x : naXs;   // t=255: tB1 is identity -> garbage harmless
        float naY = isL31 ? sA.y : naYs;
        float ux  = isL0 ? sU.x : uxs;
        float uy  = isL0 ? sU.y : uys;
        float uz  = isL0 ? sU.z : uzs;
        ux = isT0 ? 0.f : ux;              // t=0: channel 0 passes through
        uy = isT0 ? 0.f : uy;
        uz = isT0 ? 1.f : uz;

        // c3' = a-output of edge MZI; c0' = b-output of left edge MZI
        float n3r = tB1.z*p3r - tB1.w*naY;
        float n3i = tB1.z*p3i + tB1.w*naX;
        float n0r = uz*c0r - uy;
        float n0i = uz*c0i + ux;
        c3r = n3r; c3i = n3i; c0r = n0r; c0i = n0i;
    }

    // ---- epilogue (4 channels per thread) ----
    float4 ihR = ((const float4*)bR)[t];
    float4 ihI = ((const float4*)bI)[t];
    #pragma unroll
    for (int c = 0; c < 4; c++) {
        float4 pr4 = *(const float4*)&g_pR[c][b * HH + 4 * t];
        float4 pi4 = *(const float4*)&g_pI[c][b * HH + 4 * t];
        ihR.x += pr4.x; ihR.y += pr4.y; ihR.z += pr4.z; ihR.w += pr4.w;
        ihI.x += pi4.x; ihI.y += pi4.y; ihI.z += pi4.z; ihI.w += pi4.w;
    }
    float4 om4 = ((const float4*)om)[t];
    float4 mb4 = ((const float4*)mb)[t];

    float hr[4] = {c0r, c1r, c2r, c3r};
    float hi[4] = {c0i, c1i, c2i, c3i};
    float ihRa[4] = {ihR.x, ihR.y, ihR.z, ihR.w};
    float ihIa[4] = {ihI.x, ihI.y, ihI.z, ihI.w};
    float oma[4] = {om4.x, om4.y, om4.z, om4.w};
    float mba[4] = {mb4.x, mb4.y, mb4.z, mb4.w};
    float zr[4], zi[4];
    #pragma unroll
    for (int j = 0; j < 4; j++) {
        float co, so;
        sincosf(oma[j], &so, &co);
        float zrr = ihRa[j] + co*hr[j] - so*hi[j];
        float zii = ihIa[j] + so*hr[j] + co*hi[j];
        float mag = sqrtf(zrr*zrr + zii*zii);
        float sc  = fmaxf(mag + mba[j], 0.f) / fmaxf(mag, 1e-8f);
        zr[j] = sc*zrr; zi[j] = sc*zii;
    }
    ((float4*)(out + b * HH))[t]           = make_float4(zr[0], zr[1], zr[2], zr[3]);
    ((float4*)(out + BB * HH + b * HH))[t] = make_float4(zi[0], zi[1], zi[2], zi[3]);
}

// ---------------------------------------------------------------------------
extern "C" void kernel_launch(void* const* d_in, const int* in_sizes, int n_in,
                              void* d_out, int out_size)
{
    const float* inR = (const float*)d_in[0];
    const float* inI = (const float*)d_in[1];
    const float* stR = (const float*)d_in[2];
    const float* stI = (const float*)d_in[3];
    const float* wR  = (const float*)d_in[4];
    const float* wI  = (const float*)d_in[5];
    const float* bR  = (const float*)d_in[6];
    const float* bI  = (const float*)d_in[7];
    const float* A0  = (const float*)d_in[8];
    const float* A1  = (const float*)d_in[9];
    const float* B0  = (const float*)d_in[10];
    const float* B1  = (const float*)d_in[11];
    const float* om  = (const float*)d_in[12];
    const float* mb  = (const float*)d_in[13];
    float* out = (float*)d_out;

    k1<<<256, 256>>>(inR, inI, wR, wI, A0, A1, B0, B1);
    k2<<<128, 256>>>(stR, stI, bR, bI, om, mb, out);
}

// round 6
// speedup vs baseline: 1.0936x; 1.0359x over previous
#include <cuda_runtime.h>
#include <cstdint>

// Problem constants
#define BB   128   // batch
#define INW  256   // input width
#define HH   1024  // hidden
#define NP   512   // pairs per A layer
#define LP   128   // number of (A,B) layer pairs (L=256 layers total)
#define FULLMASK 0xffffffffu

// Static device scratch (padded +2 layers so depth-2 prefetch never faults)
__device__ float4 g_trigA[LP + 2][NP];      // {cos t0, sin t0, cos t1, sin t1}
__device__ float4 g_trigB[LP + 2][NP];      // idx 511 = identity MZI
__device__ float  g_pR[4][BB * HH];         // GEMM partials per K-chunk
__device__ float  g_pI[4][BB * HH];

// ---------------------------------------------------------------------------
// Kernel 1: blocks [0,128) = complex GEMM (K-split x4, N-tiles of 32)
//           blocks [128,256) = trig table build (one block per layer pair)
// ---------------------------------------------------------------------------
__global__ __launch_bounds__(256) void k1(
    const float* __restrict__ inR, const float* __restrict__ inI,
    const float* __restrict__ wR,  const float* __restrict__ wI,
    const float* __restrict__ A0,  const float* __restrict__ A1,
    const float* __restrict__ B0,  const float* __restrict__ B1)
{
    const int bid = blockIdx.x, tid = threadIdx.x;

    if (bid >= 128) {
        const int k = bid - 128;
        for (int idx = tid; idx < NP; idx += 256) {
            float c0, s0, c1, s1;
            sincosf(A0[k * NP + idx], &s0, &c0);
            sincosf(A1[k * NP + idx], &s1, &c1);
            g_trigA[k][idx] = make_float4(c0, s0, c1, s1);
        }
        for (int idx = tid; idx < NP; idx += 256) {
            float ang0 = (idx < NP - 1) ? B0[k * (NP - 1) + idx] : 0.f;
            float ang1 = (idx < NP - 1) ? B1[k * (NP - 1) + idx] : 0.f;
            float c0, s0, c1, s1;
            sincosf(ang0, &s0, &c0);
            sincosf(ang1, &s1, &c1);
            g_trigB[k][idx] = make_float4(c0, s0, c1, s1);
        }
        return;
    }

    // ---- complex GEMM: tile M=128, N=32, K-chunk=64 ----
    const int kc = bid >> 5, nt = bid & 31;
    const int k0 = kc * 64, n0 = nt * 32;

    __shared__ float sXR[32][132], sXI[32][132];
    __shared__ float sWR[32][33],  sWI[32][33];

    float accR[8][2], accI[8][2];
    #pragma unroll
    for (int r = 0; r < 8; r++)
        #pragma unroll
        for (int c = 0; c < 2; c++) { accR[r][c] = 0.f; accI[r][c] = 0.f; }

    const int mi = tid >> 4, ni = tid & 15;
    const int lm = tid & 127, kh = (tid >> 7) * 16;
    const int wn = tid >> 3,  wk = (tid & 7) * 4;

    for (int ks = 0; ks < 64; ks += 32) {
        __syncthreads();
        #pragma unroll
        for (int j = 0; j < 4; j++) {
            const int kk = kh + j * 4;
            float4 vR = *(const float4*)(inR + lm * INW + k0 + ks + kk);
            float4 vI = *(const float4*)(inI + lm * INW + k0 + ks + kk);
            sXR[kk+0][lm] = vR.x; sXR[kk+1][lm] = vR.y;
            sXR[kk+2][lm] = vR.z; sXR[kk+3][lm] = vR.w;
            sXI[kk+0][lm] = vI.x; sXI[kk+1][lm] = vI.y;
            sXI[kk+2][lm] = vI.z; sXI[kk+3][lm] = vI.w;
        }
        {
            float4 vR = *(const float4*)(wR + (n0 + wn) * INW + k0 + ks + wk);
            float4 vI = *(const float4*)(wI + (n0 + wn) * INW + k0 + ks + wk);
            sWR[wk+0][wn] = vR.x; sWR[wk+1][wn] = vR.y;
            sWR[wk+2][wn] = vR.z; sWR[wk+3][wn] = vR.w;
            sWI[wk+0][wn] = vI.x; sWI[wk+1][wn] = vI.y;
            sWI[wk+2][wn] = vI.z; sWI[wk+3][wn] = vI.w;
        }
        __syncthreads();

        #pragma unroll 8
        for (int kk = 0; kk < 32; kk++) {
            float aRv[8], aIv[8], bRv[2], bIv[2];
            *(float4*)&aRv[0] = *(const float4*)&sXR[kk][mi * 8];
            *(float4*)&aRv[4] = *(const float4*)&sXR[kk][mi * 8 + 4];
            *(float4*)&aIv[0] = *(const float4*)&sXI[kk][mi * 8];
            *(float4*)&aIv[4] = *(const float4*)&sXI[kk][mi * 8 + 4];
            bRv[0] = sWR[kk][ni*2]; bRv[1] = sWR[kk][ni*2+1];
            bIv[0] = sWI[kk][ni*2]; bIv[1] = sWI[kk][ni*2+1];
            #pragma unroll
            for (int r = 0; r < 8; r++)
                #pragma unroll
                for (int c = 0; c < 2; c++) {
                    accR[r][c] += aRv[r]*bRv[c] - aIv[r]*bIv[c];
                    accI[r][c] += aRv[r]*bIv[c] + aIv[r]*bRv[c];
                }
        }
    }

    #pragma unroll
    for (int r = 0; r < 8; r++) {
        const int m = mi * 8 + r;
        #pragma unroll
        for (int c = 0; c < 2; c++) {
            g_pR[kc][m * HH + n0 + ni*2 + c] = accR[r][c];
            g_pI[kc][m * HH + n0 + ni*2 + c] = accI[r][c];
        }
    }
}

// ---------------------------------------------------------------------------
// helpers
// ---------------------------------------------------------------------------
__device__ __forceinline__ float4 ldg_v4_pinned(const float4* p) {
    float4 v;
    asm volatile("ld.global.nc.v4.f32 {%0,%1,%2,%3}, [%4];"
                 : "=f"(v.x), "=f"(v.y), "=f"(v.z), "=f"(v.w) : "l"(p));
    return v;
}

// predicated plain shared store (ordering provided by bar.sync)
__device__ __forceinline__ void pub_pred(uint32_t addr, int pred,
                                         float x, float y, float z) {
    asm volatile("{\n\t"
                 ".reg .pred p;\n\t"
                 "setp.ne.s32 p, %0, 0;\n\t"
                 "@p st.shared.v4.f32 [%1], {%2,%3,%4,%2};\n\t"
                 "}"
                 :: "r"(pred), "r"(addr), "f"(x), "f"(y), "f"(z)
                 : "memory");
}

__device__ __forceinline__ float4 lds4(uint32_t addr) {
    float4 v;
    asm volatile("ld.shared.v4.f32 {%0,%1,%2,%3}, [%4];"
                 : "=f"(v.x), "=f"(v.y), "=f"(v.z), "=f"(v.w) : "r"(addr)
                 : "memory");
    return v;
}

__device__ __forceinline__ void named_bar(int id, int cnt) {
    asm volatile("bar.sync %0, %1;" :: "r"(id), "r"(cnt) : "memory");
}

// ---------------------------------------------------------------------------
// Kernel 2: Clements mesh — 256 threads, 4 channels/thread.
// Cross-warp handoff via pairwise 64-thread named barriers (red-black):
// waiting warps SLEEP (no issue-slot burn), publishes are plain STS.
// ---------------------------------------------------------------------------
__global__ __launch_bounds__(256, 1) void k2(
    const float* __restrict__ stR, const float* __restrict__ stI,
    const float* __restrict__ bR,  const float* __restrict__ bI,
    const float* __restrict__ om,  const float* __restrict__ mb,
    float* __restrict__ out)
{
    const int b = blockIdx.x, t = threadIdx.x;
    const int w = t >> 5, l = t & 31;

    __shared__ float4 slotA[2][8];   // c0 of warp w+1 lane0, boundary b=w
    __shared__ float4 slotU[2][8];   // u  of warp w  lane31, boundary b=w

    // thread t owns channels 4t .. 4t+3
    float4 xr = ((const float4*)(stR + b * HH))[t];
    float4 xi = ((const float4*)(stI + b * HH))[t];
    float c0r = xr.x, c1r = xr.y, c2r = xr.z, c3r = xr.w;
    float c0i = xi.x, c1i = xi.y, c2i = xi.z, c3i = xi.w;

    const uint32_t baseA = (uint32_t)__cvta_generic_to_shared(slotA);
    const uint32_t baseU = (uint32_t)__cvta_generic_to_shared(slotU);
    // publish addresses: lane0 of warp w -> slotA[b=w-1]; lane31 of warp w -> slotU[b=w]
    const uint32_t sPubA = (uint32_t)(((w > 0) ? (w - 1) : 0) * 16);
    const uint32_t sPubU = (uint32_t)(w * 16);
    // read addresses: warp w reads slotA[b=w] (right) and slotU[b=w-1] (left)
    const uint32_t sRdA  = (uint32_t)(((w < 7) ? w : 6) * 16);
    const uint32_t sRdU  = (uint32_t)(((w > 0) ? (w - 1) : 0) * 16);
    const int isL0 = (l == 0), isL31 = (l == 31), isT0 = (t == 0);
    const int pubA = isL0 && (w > 0);       // c0 crosses left boundary
    const int pubU = isL31 && (w < 7);      // u crosses right boundary
    // red-black barrier ids: even boundary = the even b in {w-1, w}; odd likewise
    const int barEvenId = 1 + (w >> 1);                       // b = w & ~1, pairs (0,1)(2,3)(4,5)(6,7)
    const int hasOdd    = (w >= 1 && w <= 6);
    const int barOddId  = 9 + ((w - 1) >> 1);                 // b odd, pairs (1,2)(3,4)(5,6)

    // depth-2 trig prefetch; thread t uses pair indices 2t, 2t+1 (contiguous)
    const float4* pA = &g_trigA[0][2 * t];
    const float4* pB = &g_trigB[0][2 * t];
    float4 a0A = ldg_v4_pinned(pA),       a1A = ldg_v4_pinned(pA + 1);
    float4 b0A = ldg_v4_pinned(pB),       b1A = ldg_v4_pinned(pB + 1);
    float4 a0B = ldg_v4_pinned(pA + NP),  a1B = ldg_v4_pinned(pA + NP + 1);
    float4 b0B = ldg_v4_pinned(pB + NP),  b1B = ldg_v4_pinned(pB + NP + 1);

    #pragma unroll 2
    for (int k = 0; k < LP; k++) {
        const uint32_t boff = (uint32_t)((k & 1) << 7);   // parity * 8 slots * 16B

        float4 tA0 = a0A, tA1 = a1A, tB0 = b0A, tB1 = b1A;
        a0A = a0B; a1A = a1B; b0A = b0B; b1A = b1B;
        a0B = ldg_v4_pinned(pA + (k + 2) * NP);
        a1B = ldg_v4_pinned(pA + (k + 2) * NP + 1);
        b0B = ldg_v4_pinned(pB + (k + 2) * NP);
        b1B = ldg_v4_pinned(pB + (k + 2) * NP + 1);

        // ---- layer A, MZI (c0,c1) ----
        {
            float pr = tA0.x*c0r - tA0.y*c0i;
            float pi = tA0.y*c0r + tA0.x*c0i;
            float n0r = tA0.z*pr  - tA0.w*c1i;
            float n0i = tA0.z*pi  + tA0.w*c1r;
            float n1r = tA0.z*c1r - tA0.w*pi;
            float n1i = tA0.z*c1i + tA0.w*pr;
            c0r = n0r; c0i = n0i; c1r = n1r; c1i = n1i;
        }
        // early publish: lane0's post-A c0 crosses the left boundary
        pub_pred(baseA + boff + sPubA, pubA, c0r, c0i, 0.f);

        // ---- layer A, MZI (c2,c3) ----
        {
            float pr = tA1.x*c2r - tA1.y*c2i;
            float pi = tA1.y*c2r + tA1.x*c2i;
            float n2r = tA1.z*pr  - tA1.w*c3i;
            float n2i = tA1.z*pi  + tA1.w*c3r;
            float n3r = tA1.z*c3r - tA1.w*pi;
            float n3i = tA1.z*c3i + tA1.w*pr;
            c2r = n2r; c2i = n2i; c3r = n3r; c3i = n3i;
        }

        // ---- edge B MZI (c3, next c0): phase + u, publish right ----
        float p3r = tB1.x*c3r - tB1.y*c3i;
        float p3i = tB1.y*c3r + tB1.x*c3i;
        float u3x = tB1.w*p3r, u3y = tB1.w*p3i, u3z = tB1.z;
        pub_pred(baseU + boff + sPubU, pubU, u3x, u3y, u3z);

        // intra-warp exchange
        float naXs = __shfl_down_sync(FULLMASK, c0r, 1);
        float naYs = __shfl_down_sync(FULLMASK, c0i, 1);
        float uxs  = __shfl_up_sync(FULLMASK, u3x, 1);
        float uys  = __shfl_up_sync(FULLMASK, u3y, 1);
        float uzs  = __shfl_up_sync(FULLMASK, u3z, 1);

        // ---- middle B MZI (c1,c2): thread-local, fills shfl latency ----
        {
            float pmr = tB0.x*c1r - tB0.y*c1i;
            float pmi = tB0.y*c1r + tB0.x*c1i;
            float n1r = tB0.z*pmr - tB0.w*c2i;
            float n1i = tB0.z*pmi + tB0.w*c2r;
            float n2r = tB0.z*c2r - tB0.w*pmi;
            float n2i = tB0.z*c2i + tB0.w*pmr;
            c1r = n1r; c1i = n1i; c2r = n2r; c2i = n2i;
        }

        // ---- red-black pairwise barriers (sleep-wait, no polling) ----
        named_bar(barEvenId, 64);
        if (hasOdd) named_bar(barOddId, 64);

        float4 sA = lds4(baseA + boff + sRdA);
        float4 sU = lds4(baseU + boff + sRdU);

        float naX = isL31 ? sA.x : naXs;   // t=255: tB1 identity -> garbage harmless
        float naY = isL31 ? sA.y : naYs;
        float ux  = isL0 ? sU.x : uxs;
        float uy  = isL0 ? sU.y : uys;
        float uz  = isL0 ? sU.z : uzs;
        ux = isT0 ? 0.f : ux;              // t=0: channel 0 passes through
        uy = isT0 ? 0.f : uy;
        uz = isT0 ? 1.f : uz;

        // c3' = a-output of edge MZI; c0' = b-output of left edge MZI
        float n3r = tB1.z*p3r - tB1.w*naY;
        float n3i = tB1.z*p3i + tB1.w*naX;
        float n0r = uz*c0r - uy;
        float n0i = uz*c0i + ux;
        c3r = n3r; c3i = n3i; c0r = n0r; c0i = n0i;
    }

    // ---- epilogue (4 channels per thread) ----
    float4 ihR = ((const float4*)bR)[t];
    float4 ihI = ((const float4*)bI)[t];
    #pragma unroll
    for (int c = 0; c < 4; c++) {
        float4 pr4 = *(const float4*)&g_pR[c][b * HH + 4 * t];
        float4 pi4 = *(const float4*)&g_pI[c][b * HH + 4 * t];
        ihR.x += pr4.x; ihR.y += pr4.y; ihR.z += pr4.z; ihR.w += pr4.w;
        ihI.x += pi4.x; ihI.y += pi4.y; ihI.z += pi4.z; ihI.w += pi4.w;
    }
    float4 om4 = ((const float4*)om)[t];
    float4 mb4 = ((const float4*)mb)[t];

    float hr[4] = {c0r, c1r, c2r, c3r};
    float hi[4] = {c0i, c1i, c2i, c3i};
    float ihRa[4] = {ihR.x, ihR.y, ihR.z, ihR.w};
    float ihIa[4] = {ihI.x, ihI.y, ihI.z, ihI.w};
    float oma[4] = {om4.x, om4.y, om4.z, om4.w};
    float mba[4] = {mb4.x, mb4.y, mb4.z, mb4.w};
    float zr[4], zi[4];
    #pragma unroll
    for (int j = 0; j < 4; j++) {
        float co, so;
        sincosf(oma[j], &so, &co);
        float zrr = ihRa[j] + co*hr[j] - so*hi[j];
        float zii = ihIa[j] + so*hr[j] + co*hi[j];
        float mag = sqrtf(zrr*zrr + zii*zii);
        float sc  = fmaxf(mag + mba[j], 0.f) / fmaxf(mag, 1e-8f);
        zr[j] = sc*zrr; zi[j] = sc*zii;
    }
    ((float4*)(out + b * HH))[t]           = make_float4(zr[0], zr[1], zr[2], zr[3]);
    ((float4*)(out + BB * HH + b * HH))[t] = make_float4(zi[0], zi[1], zi[2], zi[3]);
}

// ---------------------------------------------------------------------------
extern "C" void kernel_launch(void* const* d_in, const int* in_sizes, int n_in,
                              void* d_out, int out_size)
{
    const float* inR = (const float*)d_in[0];
    const float* inI = (const float*)d_in[1];
    const float* stR = (const float*)d_in[2];
    const float* stI = (const float*)d_in[3];
    const float* wR  = (const float*)d_in[4];
    const float* wI  = (const float*)d_in[5];
    const float* bR  = (const float*)d_in[6];
    const float* bI  = (const float*)d_in[7];
    const float* A0  = (const float*)d_in[8];
    const float* A1  = (const float*)d_in[9];
    const float* B0  = (const float*)d_in[10];
    const float* B1  = (const float*)d_in[11];
    const float* om  = (const float*)d_in[12];
    const float* mb  = (const float*)d_in[13];
    float* out = (float*)d_out;

    k1<<<256, 256>>>(inR, inI, wR, wI, A0, A1, B0, B1);
    k2<<<128, 256>>>(stR, stI, bR, bI, om, mb, out);
}

// round 7
// speedup vs baseline: 1.2007x; 1.0979x over previous
#include <cuda_runtime.h>
#include <cstdint>

// Problem constants
#define BB   128   // batch
#define INW  256   // input width
#define HH   1024  // hidden
#define NP   512   // pairs per A layer
#define LP   128   // number of (A,B) layer pairs (L=256 layers total)
#define FULLMASK 0xffffffffu

// Transposed trig tables: [layer][j][thread] so lane stride is 16B (coalesced).
// j in {0,1}: A-layer pair 2t+j. For B: j=0 -> middle MZI pair 2t, j=1 -> edge pair 2t+1.
// Padded +2 layers so depth-2 prefetch never faults.
__device__ float4 g_tA[LP + 2][2][256];
__device__ float4 g_tB[LP + 2][2][256];
__device__ float  g_pR[4][BB * HH];         // GEMM partials per K-chunk
__device__ float  g_pI[4][BB * HH];

// ---------------------------------------------------------------------------
// Kernel 1: blocks [0,128) = complex GEMM (K-split x4, N-tiles of 32)
//           blocks [128,256) = trig table build (one block per layer pair)
// ---------------------------------------------------------------------------
__global__ __launch_bounds__(256) void k1(
    const float* __restrict__ inR, const float* __restrict__ inI,
    const float* __restrict__ wR,  const float* __restrict__ wI,
    const float* __restrict__ A0,  const float* __restrict__ A1,
    const float* __restrict__ B0,  const float* __restrict__ B1)
{
    const int bid = blockIdx.x, tid = threadIdx.x;

    if (bid >= 128) {
        const int k = bid - 128;
        for (int idx = tid; idx < NP; idx += 256) {
            float c0, s0, c1, s1;
            sincosf(A0[k * NP + idx], &s0, &c0);
            sincosf(A1[k * NP + idx], &s1, &c1);
            g_tA[k][idx & 1][idx >> 1] = make_float4(c0, s0, c1, s1);
        }
        for (int idx = tid; idx < NP; idx += 256) {
            float ang0 = (idx < NP - 1) ? B0[k * (NP - 1) + idx] : 0.f;
            float ang1 = (idx < NP - 1) ? B1[k * (NP - 1) + idx] : 0.f;
            float c0, s0, c1, s1;
            sincosf(ang0, &s0, &c0);
            sincosf(ang1, &s1, &c1);
            g_tB[k][idx & 1][idx >> 1] = make_float4(c0, s0, c1, s1);
        }
        return;
    }

    // ---- complex GEMM: tile M=128, N=32, K-chunk=64 ----
    const int kc = bid >> 5, nt = bid & 31;
    const int k0 = kc * 64, n0 = nt * 32;

    __shared__ float sXR[32][132], sXI[32][132];
    __shared__ float sWR[32][33],  sWI[32][33];

    float accR[8][2], accI[8][2];
    #pragma unroll
    for (int r = 0; r < 8; r++)
        #pragma unroll
        for (int c = 0; c < 2; c++) { accR[r][c] = 0.f; accI[r][c] = 0.f; }

    const int mi = tid >> 4, ni = tid & 15;
    const int lm = tid & 127, kh = (tid >> 7) * 16;
    const int wn = tid >> 3,  wk = (tid & 7) * 4;

    for (int ks = 0; ks < 64; ks += 32) {
        __syncthreads();
        #pragma unroll
        for (int j = 0; j < 4; j++) {
            const int kk = kh + j * 4;
            float4 vR = *(const float4*)(inR + lm * INW + k0 + ks + kk);
            float4 vI = *(const float4*)(inI + lm * INW + k0 + ks + kk);
            sXR[kk+0][lm] = vR.x; sXR[kk+1][lm] = vR.y;
            sXR[kk+2][lm] = vR.z; sXR[kk+3][lm] = vR.w;
            sXI[kk+0][lm] = vI.x; sXI[kk+1][lm] = vI.y;
            sXI[kk+2][lm] = vI.z; sXI[kk+3][lm] = vI.w;
        }
        {
            float4 vR = *(const float4*)(wR + (n0 + wn) * INW + k0 + ks + wk);
            float4 vI = *(const float4*)(wI + (n0 + wn) * INW + k0 + ks + wk);
            sWR[wk+0][wn] = vR.x; sWR[wk+1][wn] = vR.y;
            sWR[wk+2][wn] = vR.z; sWR[wk+3][wn] = vR.w;
            sWI[wk+0][wn] = vI.x; sWI[wk+1][wn] = vI.y;
            sWI[wk+2][wn] = vI.z; sWI[wk+3][wn] = vI.w;
        }
        __syncthreads();

        #pragma unroll 8
        for (int kk = 0; kk < 32; kk++) {
            float aRv[8], aIv[8], bRv[2], bIv[2];
            *(float4*)&aRv[0] = *(const float4*)&sXR[kk][mi * 8];
            *(float4*)&aRv[4] = *(const float4*)&sXR[kk][mi * 8 + 4];
            *(float4*)&aIv[0] = *(const float4*)&sXI[kk][mi * 8];
            *(float4*)&aIv[4] = *(const float4*)&sXI[kk][mi * 8 + 4];
            bRv[0] = sWR[kk][ni*2]; bRv[1] = sWR[kk][ni*2+1];
            bIv[0] = sWI[kk][ni*2]; bIv[1] = sWI[kk][ni*2+1];
            #pragma unroll
            for (int r = 0; r < 8; r++)
                #pragma unroll
                for (int c = 0; c < 2; c++) {
                    accR[r][c] += aRv[r]*bRv[c] - aIv[r]*bIv[c];
                    accI[r][c] += aRv[r]*bIv[c] + aIv[r]*bRv[c];
                }
        }
    }

    #pragma unroll
    for (int r = 0; r < 8; r++) {
        const int m = mi * 8 + r;
        #pragma unroll
        for (int c = 0; c < 2; c++) {
            g_pR[kc][m * HH + n0 + ni*2 + c] = accR[r][c];
            g_pI[kc][m * HH + n0 + ni*2 + c] = accI[r][c];
        }
    }
}

// ---------------------------------------------------------------------------
// helpers
// ---------------------------------------------------------------------------
__device__ __forceinline__ float4 ldg_v4_pinned(const float4* p) {
    float4 v;
    asm volatile("ld.global.nc.v4.f32 {%0,%1,%2,%3}, [%4];"
                 : "=f"(v.x), "=f"(v.y), "=f"(v.z), "=f"(v.w) : "l"(p));
    return v;
}

// predicated plain shared store (ordering provided by __syncthreads)
__device__ __forceinline__ void pub_pred(uint32_t addr, int pred,
                                         float x, float y, float z) {
    asm volatile("{\n\t"
                 ".reg .pred p;\n\t"
                 "setp.ne.s32 p, %0, 0;\n\t"
                 "@p st.shared.v4.f32 [%1], {%2,%3,%4,%2};\n\t"
                 "}"
                 :: "r"(pred), "r"(addr), "f"(x), "f"(y), "f"(z)
                 : "memory");
}

__device__ __forceinline__ float4 lds4(uint32_t addr) {
    float4 v;
    asm volatile("ld.shared.v4.f32 {%0,%1,%2,%3}, [%4];"
                 : "=f"(v.x), "=f"(v.y), "=f"(v.z), "=f"(v.w) : "r"(addr)
                 : "memory");
    return v;
}

// ---------------------------------------------------------------------------
// Kernel 2: Clements mesh — 256 threads, 4 channels/thread.
// Coalesced (transposed) trig loads, depth-2 register prefetch,
// ONE __syncthreads per layer pair, parity double-buffered boundary slots.
// ---------------------------------------------------------------------------
__global__ __launch_bounds__(256, 1) void k2(
    const float* __restrict__ stR, const float* __restrict__ stI,
    const float* __restrict__ bR,  const float* __restrict__ bI,
    const float* __restrict__ om,  const float* __restrict__ mb,
    float* __restrict__ out)
{
    const int b = blockIdx.x, t = threadIdx.x;
    const int w = t >> 5, l = t & 31;

    __shared__ float4 slotA[2][8];   // boundary b=w: c0 of warp w+1 lane0
    __shared__ float4 slotU[2][8];   // boundary b=w: u  of warp w  lane31

    // thread t owns channels 4t .. 4t+3
    float4 xr = ((const float4*)(stR + b * HH))[t];
    float4 xi = ((const float4*)(stI + b * HH))[t];
    float c0r = xr.x, c1r = xr.y, c2r = xr.z, c3r = xr.w;
    float c0i = xi.x, c1i = xi.y, c2i = xi.z, c3i = xi.w;

    const uint32_t baseA = (uint32_t)__cvta_generic_to_shared(slotA);
    const uint32_t baseU = (uint32_t)__cvta_generic_to_shared(slotU);
    const uint32_t sPubA = (uint32_t)(((w > 0) ? (w - 1) : 0) * 16);
    const uint32_t sPubU = (uint32_t)(w * 16);
    const uint32_t sRdA  = (uint32_t)(((w < 7) ? w : 6) * 16);
    const uint32_t sRdU  = (uint32_t)(((w > 0) ? (w - 1) : 0) * 16);
    const int isL0 = (l == 0), isL31 = (l == 31), isT0 = (t == 0);
    const int pubA = isL0 && (w > 0);
    const int pubU = isL31 && (w < 7);

    // coalesced trig streams: lane stride 16B
    const float4* pA0 = &g_tA[0][0][t];   // layer stride = 512 float4
    const float4* pA1 = &g_tA[0][1][t];
    const float4* pB0 = &g_tB[0][0][t];
    const float4* pB1 = &g_tB[0][1][t];

    // depth-2 register prefetch
    float4 a0A = ldg_v4_pinned(pA0),        a1A = ldg_v4_pinned(pA1);
    float4 b0A = ldg_v4_pinned(pB0),        b1A = ldg_v4_pinned(pB1);
    float4 a0B = ldg_v4_pinned(pA0 + 512),  a1B = ldg_v4_pinned(pA1 + 512);
    float4 b0B = ldg_v4_pinned(pB0 + 512),  b1B = ldg_v4_pinned(pB1 + 512);

    #pragma unroll 2
    for (int k = 0; k < LP; k++) {
        const uint32_t boff = (uint32_t)((k & 1) << 7);   // parity * 8 slots * 16B

        float4 tA0 = a0A, tA1 = a1A, tB0 = b0A, tB1 = b1A;
        a0A = a0B; a1A = a1B; b0A = b0B; b1A = b1B;
        const int off = (k + 2) * 512;
        a0B = ldg_v4_pinned(pA0 + off);
        a1B = ldg_v4_pinned(pA1 + off);
        b0B = ldg_v4_pinned(pB0 + off);
        b1B = ldg_v4_pinned(pB1 + off);

        // ---- layer A, MZI (c0,c1) ----
        {
            float pr = tA0.x*c0r - tA0.y*c0i;
            float pi = tA0.y*c0r + tA0.x*c0i;
            float n0r = tA0.z*pr  - tA0.w*c1i;
            float n0i = tA0.z*pi  + tA0.w*c1r;
            float n1r = tA0.z*c1r - tA0.w*pi;
            float n1i = tA0.z*c1i + tA0.w*pr;
            c0r = n0r; c0i = n0i; c1r = n1r; c1i = n1i;
        }
        // early publish: lane0's post-A c0 crosses the left boundary
        pub_pred(baseA + boff + sPubA, pubA, c0r, c0i, 0.f);

        // ---- layer A, MZI (c2,c3) ----
        {
            float pr = tA1.x*c2r - tA1.y*c2i;
            float pi = tA1.y*c2r + tA1.x*c2i;
            float n2r = tA1.z*pr  - tA1.w*c3i;
            float n2i = tA1.z*pi  + tA1.w*c3r;
            float n3r = tA1.z*c3r - tA1.w*pi;
            float n3i = tA1.z*c3i + tA1.w*pr;
            c2r = n2r; c2i = n2i; c3r = n3r; c3i = n3i;
        }

        // ---- edge B MZI (c3, next c0): phase + u, publish right ----
        float p3r = tB1.x*c3r - tB1.y*c3i;
        float p3i = tB1.y*c3r + tB1.x*c3i;
        float u3x = tB1.w*p3r, u3y = tB1.w*p3i, u3z = tB1.z;
        pub_pred(baseU + boff + sPubU, pubU, u3x, u3y, u3z);

        // intra-warp exchange
        float naXs = __shfl_down_sync(FULLMASK, c0r, 1);
        float naYs = __shfl_down_sync(FULLMASK, c0i, 1);
        float uxs  = __shfl_up_sync(FULLMASK, u3x, 1);
        float uys  = __shfl_up_sync(FULLMASK, u3y, 1);
        float uzs  = __shfl_up_sync(FULLMASK, u3z, 1);

        // ---- middle B MZI (c1,c2): thread-local, fills shfl latency ----
        {
            float pmr = tB0.x*c1r - tB0.y*c1i;
            float pmi = tB0.y*c1r + tB0.x*c1i;
            float n1r = tB0.z*pmr - tB0.w*c2i;
            float n1i = tB0.z*pmi + tB0.w*c2r;
            float n2r = tB0.z*c2r - tB0.w*pmi;
            float n2i = tB0.z*c2i + tB0.w*pmr;
            c1r = n1r; c1i = n1i; c2r = n2r; c2i = n2i;
        }

        __syncthreads();   // single CTA barrier per layer pair

        float4 sA = lds4(baseA + boff + sRdA);
        float4 sU = lds4(baseU + boff + sRdU);

        float naX = isL31 ? sA.x : naXs;   // t=255: tB1 identity -> garbage harmless
        float naY = isL31 ? sA.y : naYs;
        float ux  = isL0 ? sU.x : uxs;
        float uy  = isL0 ? sU.y : uys;
        float uz  = isL0 ? sU.z : uzs;
        ux = isT0 ? 0.f : ux;              // t=0: channel 0 passes through
        uy = isT0 ? 0.f : uy;
        uz = isT0 ? 1.f : uz;

        // c3' = a-output of edge MZI; c0' = b-output of left edge MZI
        float n3r = tB1.z*p3r - tB1.w*naY;
        float n3i = tB1.z*p3i + tB1.w*naX;
        float n0r = uz*c0r - uy;
        float n0i = uz*c0i + ux;
        c3r = n3r; c3i = n3i; c0r = n0r; c0i = n0i;
    }

    // ---- epilogue (4 channels per thread) ----
    float4 ihR = ((const float4*)bR)[t];
    float4 ihI = ((const float4*)bI)[t];
    #pragma unroll
    for (int c = 0; c < 4; c++) {
        float4 pr4 = *(const float4*)&g_pR[c][b * HH + 4 * t];
        float4 pi4 = *(const float4*)&g_pI[c][b * HH + 4 * t];
        ihR.x += pr4.x; ihR.y += pr4.y; ihR.z += pr4.z; ihR.w += pr4.w;
        ihI.x += pi4.x; ihI.y += pi4.y; ihI.z += pi4.z; ihI.w += pi4.w;
    }
    float4 om4 = ((const float4*)om)[t];
    float4 mb4 = ((const float4*)mb)[t];

    float hr[4] = {c0r, c1r, c2r, c3r};
    float hi[4] = {c0i, c1i, c2i, c3i};
    float ihRa[4] = {ihR.x, ihR.y, ihR.z, ihR.w};
    float ihIa[4] = {ihI.x, ihI.y, ihI.z, ihI.w};
    float oma[4] = {om4.x, om4.y, om4.z, om4.w};
    float mba[4] = {mb4.x, mb4.y, mb4.z, mb4.w};
    float zr[4], zi[4];
    #pragma unroll
    for (int j = 0; j < 4; j++) {
        float co, so;
        sincosf(oma[j], &so, &co);
        float zrr = ihRa[j] + co*hr[j] - so*hi[j];
        float zii = ihIa[j] + so*hr[j] + co*hi[j];
        float mag = sqrtf(zrr*zrr + zii*zii);
        float sc  = fmaxf(mag + mba[j], 0.f) / fmaxf(mag, 1e-8f);
        zr[j] = sc*zrr; zi[j] = sc*zii;
    }
    ((float4*)(out + b * HH))[t]           = make_float4(zr[0], zr[1], zr[2], zr[3]);
    ((float4*)(out + BB * HH + b * HH))[t] = make_float4(zi[0], zi[1], zi[2], zi[3]);
}

// ---------------------------------------------------------------------------
extern "C" void kernel_launch(void* const* d_in, const int* in_sizes, int n_in,
                              void* d_out, int out_size)
{
    const float* inR = (const float*)d_in[0];
    const float* inI = (const float*)d_in[1];
    const float* stR = (const float*)d_in[2];
    const float* stI = (const float*)d_in[3];
    const float* wR  = (const float*)d_in[4];
    const float* wI  = (const float*)d_in[5];
    const float* bR  = (const float*)d_in[6];
    const float* bI  = (const float*)d_in[7];
    const float* A0  = (const float*)d_in[8];
    const float* A1  = (const float*)d_in[9];
    const float* B0  = (const float*)d_in[10];
    const float* B1  = (const float*)d_in[11];
    const float* om  = (const float*)d_in[12];
    const float* mb  = (const float*)d_in[13];
    float* out = (float*)d_out;

    k1<<<256, 256>>>(inR, inI, wR, wI, A0, A1, B0, B1);
    k2<<<128, 256>>>(stR, stI, bR, bI, om, mb, out);
}